// round 12
// baseline (speedup 1.0000x reference)
#include <cuda_runtime.h>
#include <cuda_bf16.h>

// ============================================================================
// SNN forward, factorized per-layer across time, numerics replicating the
// XLA:CPU reference bit-exactly:
//  - scans (encoder / LIF / LI): unfused __fmul_rn/__fadd_rn (LLVM CPU does
//    not contract mul+add)
//  - GEMMs: Eigen gebp accumulation order. Per output element:
//        acc = 0; for each k-panel of kc=320 (ascending):
//            p = ascending fused-FMA chain over the panel; acc = acc + p
//    (Eigen computeProductBlockingSizes caps kc at 320 for f32; mr/nr/mc/nc
//    and threading do not affect per-element k-order.)
// ============================================================================

constexpr int BATCH  = 2048;
constexpr int TSTEPS = 32;
constexpr int F_IN   = 2048;
constexpr int KC     = 320;      // Eigen f32 kc cap

// ---- scratch (static __device__ arrays: no allocations allowed) ------------
__device__ float    g_C [(size_t)TSTEPS * BATCH * 512];   // 128 MB, reused per layer
__device__ unsigned g_Z0[(size_t)BATCH * F_IN];           // encoder spikes, t-bit packed
__device__ unsigned g_S1[(size_t)BATCH * 512];
__device__ unsigned g_S2[(size_t)BATCH * 512];
__device__ unsigned g_S3[(size_t)BATCH * 256];

// ---- packed f32x2 helpers (lane-wise IEEE RN, identical to scalar ops) -----
__device__ __forceinline__ unsigned long long pack2(float lo, float hi) {
    unsigned long long r;
    asm("mov.b64 %0, {%1, %2};" : "=l"(r) : "f"(lo), "f"(hi));
    return r;
}
__device__ __forceinline__ float2 unpack2(unsigned long long v) {
    float2 r;
    asm("mov.b64 {%0, %1}, %2;" : "=f"(r.x), "=f"(r.y) : "l"(v));
    return r;
}
__device__ __forceinline__ unsigned long long add2(unsigned long long a,
                                                   unsigned long long b) {
    unsigned long long r;
    asm("add.rn.f32x2 %0, %1, %2;" : "=l"(r) : "l"(a), "l"(b));
    return r;
}
#define FFMA2(acc, a, b) \
    asm("fma.rn.f32x2 %0, %1, %2, %0;" : "+l"(acc) : "l"(a), "l"(b))

// ============================================================================
// Encoder: ConstantCurrentLIFEncoder on current = (2*fs)*x, 32 steps, pack bits.
// Unfused arithmetic (XLA:CPU per-op rounding).
// ============================================================================
__global__ void encoder_kernel(const float* __restrict__ x,
                               unsigned* __restrict__ Zbits,
                               const float* __restrict__ fs)
{
    int idx = blockIdx.x * blockDim.x + threadIdx.x;   // b * F_IN + f
    float c = __fmul_rn(__fmul_rn(2.0f, fs[0]), x[idx]);
    float v = 0.0f;
    unsigned bits = 0u;
#pragma unroll
    for (int t = 0; t < TSTEPS; t++) {
        float t1 = __fadd_rn(c, -v);          // (-v + c)
        float t2 = __fmul_rn(0.1f, t1);
        v = __fadd_rn(v, t2);
        bool z = __fadd_rn(v, -0.33f) > 0.0f;
        if (z) v = 0.0f;                      // v - z*v -> exactly +0
        bits |= (z ? 1u : 0u) << t;
    }
    Zbits[idx] = bits;
}

// ============================================================================
// GEMM over binary (bit-packed) A, Eigen-gebp accumulation order:
//   per element: panels of KC=320 ascending; within panel ascending fused-FMA
//   chain into p; at panel end: acc = acc + p.
// Row block = 4 timesteps x 32 batch rows (shared packed bit words).
// Tile 128m x 64n x 16k; per-thread 8m x 4n microtile (2 packed f32x2 pairs).
// Register prefetch pipeline over k-tiles.
// ============================================================================
__global__ __launch_bounds__(256)
void gemm_bits_kernel(const unsigned* __restrict__ bits,   // [BATCH, K] words
                      const float*    __restrict__ W,      // [N, K] row-major
                      float*          __restrict__ C,      // [T, BATCH, N]
                      int K, int N,
                      const float* __restrict__ amp_ptr, float amp_mul)
{
    const int t0 = (blockIdx.y >> 6) * 4;       // 8 t-blocks
    const int b0 = (blockIdx.y & 63) * 32;      // 64 b-blocks
    const int n0 = blockIdx.x * 64;

    float amp = amp_mul;
    if (amp_ptr) amp = __fmul_rn(amp_mul, amp_ptr[0]);

    __shared__ float As[16][132];   // [k][m]
    __shared__ float Bs[16][72];    // [k][n]

    const int tid = threadIdx.x;
    const int tm0 = (tid >> 4) << 3;            // 0..120
    const int tn0 = (tid & 15) << 2;            // 0..60

    // A loader: lm = m row (0..127), lk = k-half (0/8); m = dt*32 + db
    const int lm  = tid >> 1;
    const int lk  = (tid & 1) << 3;
    const int db  = lm & 31;
    const int dtt = t0 + (lm >> 5);
    const unsigned* zbase = bits + (size_t)(b0 + db) * K + lk;

    // B loader: 64 rows x 16 k, 4 floats/thread
    const int lm2 = tid >> 2;                   // 0..63
    const int lk2 = (tid & 3) << 2;             // 0,4,8,12
    const bool  bvalid = (n0 + lm2) < N;
    const float* wbase = W + (size_t)(n0 + (bvalid ? lm2 : 0)) * K + lk2;

    // panel partial p and panel sum acc: 8 m x 2 packed-n pairs
    unsigned long long p[8][2], acc[8][2];
#pragma unroll
    for (int i = 0; i < 8; i++) {
        p[i][0] = p[i][1] = 0ull;
        acc[i][0] = acc[i][1] = 0ull;
    }

    // ---- prefetch tile 0 ----
    uint4  z0 = *(const uint4*)(zbase);
    uint4  z1 = *(const uint4*)(zbase + 4);
    float4 q0;
    if (bvalid) q0 = *(const float4*)(wbase);
    else        q0 = make_float4(0.f, 0.f, 0.f, 0.f);

    int kin = 0;                                // position within current panel
    for (int k0 = 0; k0 < K; k0 += 16) {
        // ---- stage A (expand spike bits for this row's t) ----
        As[lk + 0][lm] = ((z0.x >> dtt) & 1u) ? amp : 0.0f;
        As[lk + 1][lm] = ((z0.y >> dtt) & 1u) ? amp : 0.0f;
        As[lk + 2][lm] = ((z0.z >> dtt) & 1u) ? amp : 0.0f;
        As[lk + 3][lm] = ((z0.w >> dtt) & 1u) ? amp : 0.0f;
        As[lk + 4][lm] = ((z1.x >> dtt) & 1u) ? amp : 0.0f;
        As[lk + 5][lm] = ((z1.y >> dtt) & 1u) ? amp : 0.0f;
        As[lk + 6][lm] = ((z1.z >> dtt) & 1u) ? amp : 0.0f;
        As[lk + 7][lm] = ((z1.w >> dtt) & 1u) ? amp : 0.0f;
        // ---- stage B ----
        Bs[lk2 + 0][lm2] = q0.x;  Bs[lk2 + 1][lm2] = q0.y;
        Bs[lk2 + 2][lm2] = q0.z;  Bs[lk2 + 3][lm2] = q0.w;
        __syncthreads();

        // ---- prefetch next tile ----
        if (k0 + 16 < K) {
            z0 = *(const uint4*)(zbase + k0 + 16);
            z1 = *(const uint4*)(zbase + k0 + 20);
            if (bvalid) q0 = *(const float4*)(wbase + k0 + 16);
        }

        // ---- ascending-k fused-FMA chain into panel partial p ----
#pragma unroll
        for (int k = 0; k < 16; k++) {
            float4 a0 = *(const float4*)&As[k][tm0];
            float4 a1 = *(const float4*)&As[k][tm0 + 4];
            ulonglong2 bq = *(const ulonglong2*)&Bs[k][tn0];
            unsigned long long bb0 = bq.x, bb1 = bq.y;
            float av[8] = {a0.x, a0.y, a0.z, a0.w, a1.x, a1.y, a1.z, a1.w};
#pragma unroll
            for (int i = 0; i < 8; i++) {
                unsigned long long aa = pack2(av[i], av[i]);
                FFMA2(p[i][0], aa, bb0);
                FFMA2(p[i][1], aa, bb1);
            }
        }

        // ---- Eigen panel boundary: acc += p (kc=320 or end of K) ----
        kin += 16;
        if (kin == KC || k0 + 16 >= K) {
#pragma unroll
            for (int i = 0; i < 8; i++) {
#pragma unroll
                for (int j = 0; j < 2; j++) {
                    acc[i][j] = add2(acc[i][j], p[i][j]);
                    p[i][j] = 0ull;
                }
            }
            kin = 0;
        }
        __syncthreads();
    }

    // ---- epilogue: scatter acc to C[t][b][n] ----
#pragma unroll
    for (int i = 0; i < 8; i++) {
        int m = tm0 + i;
        int t = t0 + (m >> 5);
        int b = b0 + (m & 31);
        float* cr = C + ((size_t)t * BATCH + b) * N;
        float2 f0 = unpack2(acc[i][0]);
        float2 f1 = unpack2(acc[i][1]);
        int n = n0 + tn0;
        if (n     < N) cr[n]     = f0.x;
        if (n + 1 < N) cr[n + 1] = f0.y;
        if (n + 2 < N) cr[n + 2] = f1.x;
        if (n + 3 < N) cr[n + 3] = f1.y;
    }
}

// ============================================================================
// LIF scan over t per (b, n): consumes C[t][b][n], emits packed spike bits.
// Unfused arithmetic:
//   v_dec = v + 0.1*(-v + i)  (OLD i);  z = (v_dec - 0.33) > 0
//   v = v_dec*(1-z);  i = i*0.8 + inp_t
// ============================================================================
__global__ void lif_scan_kernel(const float* __restrict__ C,
                                unsigned* __restrict__ Sbits, int N)
{
    int idx = blockIdx.x * blockDim.x + threadIdx.x;   // b * N + n
    int total = BATCH * N;
    float v = 0.0f, i = 0.0f;
    unsigned bits = 0u;
    const float* p = C + idx;
#pragma unroll
    for (int t = 0; t < TSTEPS; t++) {
        float c = p[(size_t)t * total];
        float t1 = __fadd_rn(i, -v);
        float t2 = __fmul_rn(0.1f, t1);
        float vd = __fadd_rn(v, t2);
        bool z = __fadd_rn(vd, -0.33f) > 0.0f;
        v = z ? 0.0f : vd;
        bits |= (z ? 1u : 0u) << t;
        i = __fadd_rn(__fmul_rn(i, 0.8f), c);
    }
    Sbits[idx] = bits;
}

// ============================================================================
// LI decoder (unfused): vo = vo + 0.1*(-vo + io) (old io); io = io*0.8 + inp_t.
// ============================================================================
__global__ void decode_kernel(const float* __restrict__ Co,   // [T, B, 100]
                              float* __restrict__ out)        // [B, 100]
{
    int idx = blockIdx.x * blockDim.x + threadIdx.x;   // b * 100 + c
    const int total = BATCH * 100;
    float vo = 0.0f, io = 0.0f;
    const float* p = Co + idx;
#pragma unroll
    for (int t = 0; t < TSTEPS; t++) {
        float c = p[(size_t)t * total];
        float t1 = __fadd_rn(io, -vo);
        float t2 = __fmul_rn(0.1f, t1);
        vo = __fadd_rn(vo, t2);
        io = __fadd_rn(__fmul_rn(io, 0.8f), c);
    }
    out[idx] = vo;
}

// ============================================================================
// Launch sequence (graph-capturable: kernel launches only, no sync/alloc)
// ============================================================================
extern "C" void kernel_launch(void* const* d_in, const int* in_sizes, int n_in,
                              void* d_out, int out_size)
{
    const float* x     = (const float*)d_in[0];
    const float* w1    = (const float*)d_in[1];   // [512, 2048]
    const float* w2    = (const float*)d_in[2];   // [512, 512]
    const float* w3    = (const float*)d_in[3];   // [256, 512]
    const float* w_out = (const float*)d_in[4];   // [100, 256]
    const float* fs    = (const float*)d_in[5];
    const float* es    = (const float*)d_in[6];
    float* out = (float*)d_out;

    void *pC, *pZ0, *pS1, *pS2, *pS3;
    cudaGetSymbolAddress(&pC,  g_C);
    cudaGetSymbolAddress(&pZ0, g_Z0);
    cudaGetSymbolAddress(&pS1, g_S1);
    cudaGetSymbolAddress(&pS2, g_S2);
    cudaGetSymbolAddress(&pS3, g_S3);
    float*    C  = (float*)pC;
    unsigned* Z0 = (unsigned*)pZ0;
    unsigned* S1 = (unsigned*)pS1;
    unsigned* S2 = (unsigned*)pS2;
    unsigned* S3 = (unsigned*)pS3;

    const int ROWBLKS = (TSTEPS / 4) * (BATCH / 32);   // 512

    // encoder -> Z0 bits
    encoder_kernel<<<(BATCH * F_IN) / 256, 256>>>(x, Z0, fs);

    // layer 1: C1 = (5*es) * Z0 @ w1^T    [32,2048,512]
    gemm_bits_kernel<<<dim3(8, ROWBLKS), 256>>>(Z0, w1, C, 2048, 512, es, 5.0f);
    lif_scan_kernel<<<(BATCH * 512) / 256, 256>>>(C, S1, 512);

    // layer 2: C2 = S1 @ w2^T             [32,2048,512]
    gemm_bits_kernel<<<dim3(8, ROWBLKS), 256>>>(S1, w2, C, 512, 512, nullptr, 1.0f);
    lif_scan_kernel<<<(BATCH * 512) / 256, 256>>>(C, S2, 512);

    // layer 3: C3 = S2 @ w3^T             [32,2048,256]
    gemm_bits_kernel<<<dim3(4, ROWBLKS), 256>>>(S2, w3, C, 512, 256, nullptr, 1.0f);
    lif_scan_kernel<<<(BATCH * 256) / 256, 256>>>(C, S3, 256);

    // output layer: Co = S3 @ w_out^T     [32,2048,100]
    gemm_bits_kernel<<<dim3(2, ROWBLKS), 256>>>(S3, w_out, C, 256, 100, nullptr, 1.0f);

    // LI decode -> final membrane voltage
    decode_kernel<<<(BATCH * 100) / 256, 256>>>(C, out);
}